// round 9
// baseline (speedup 1.0000x reference)
#include <cuda_runtime.h>
#include <cuda_fp16.h>
#include <math.h>
#include <stdint.h>

#define N_PIX 4096
#define CDIM  256
#define HID   128
#define NH    4
#define DH    32
#define BATCH 2
#define ATT_SCALE 0.17677669529663687f   // 32^-0.5
#define LOG2E     1.4426950408889634f

// ---------------- scratch (static device globals; no allocs) ----------------
__device__ __half g_qh [BATCH * NH * N_PIX * DH];   // [bh][n][f], pre-scaled by ATT_SCALE*LOG2E
__device__ __half g_kh [BATCH * NH * N_PIX * DH];   // [bh][n][f]
__device__ __half g_vh [BATCH * NH * DH * N_PIX];   // [bh][f][n]  (transposed)
__device__ __half g_aoh[BATCH * N_PIX * HID];       // [b][n][h*32+f]  (n-major)

__device__ __forceinline__ float ex2f(float x) {
    float r;
    asm("ex2.approx.f32 %0, %1;" : "=f"(r) : "f"(x));
    return r;
}
__device__ __forceinline__ uint32_t smem_u32(const void* p) {
    uint32_t a;
    asm("{ .reg .u64 t; cvta.to.shared.u64 t, %1; cvt.u32.u64 %0, t; }" : "=r"(a) : "l"(p));
    return a;
}
__device__ __forceinline__ uint32_t h2u(__half2 h) { return *(uint32_t*)&h; }

#define MMA_F16(c, a, b0_, b1_) \
    asm volatile("mma.sync.aligned.m16n8k16.row.col.f32.f16.f16.f32 " \
        "{%0,%1,%2,%3},{%4,%5,%6,%7},{%8,%9},{%0,%1,%2,%3};" \
        : "+f"((c)[0]), "+f"((c)[1]), "+f"((c)[2]), "+f"((c)[3]) \
        : "r"((a)[0]), "r"((a)[1]), "r"((a)[2]), "r"((a)[3]), "r"(b0_), "r"(b1_))
#define CP_ASYNC16(dst, src) \
    asm volatile("cp.async.ca.shared.global [%0], [%1], 16;" :: "r"(dst), "l"(src))
#define CP_COMMIT() asm volatile("cp.async.commit_group;" ::: "memory")
#define CP_WAIT0()  asm volatile("cp.async.wait_group 0;"  ::: "memory")

// ---------------- kernel 1: QKV GEMM, norm fused, software-pipelined ----------------
#define GP 12     // smem pitch in uint32 (8 half2 data + 4 pad)
__global__ void __launch_bounds__(256) qkv_mma(const float* __restrict__ x,
                                               const float* __restrict__ gvec,
                                               const float* __restrict__ w) {
    __shared__ uint32_t As[2][128 * GP];
    __shared__ uint32_t Bs[2][128 * GP];
    __shared__ float ssb[256];
    int b = blockIdx.z, row0 = blockIdx.y * 128, col0 = blockIdx.x * 128;
    int tid = threadIdx.x, wid = tid >> 5, lane = tid & 31;
    int wm = wid >> 2, wn = wid & 3;
    int g = lane >> 2, tig = lane & 3;
    const float* Bbase = x + (size_t)b * CDIM * N_PIX;

    int am = tid >> 2, aq = tid & 3;     // A-load: rows am, am+64; col quad aq
    int bp = tid & 127, bc = tid >> 7;   // B-load: pixel bp; c-quads bc, bc+2

    float acc[4][4][4];
#pragma unroll
    for (int mi = 0; mi < 4; mi++)
#pragma unroll
        for (int ni = 0; ni < 4; ni++)
#pragma unroll
            for (int i = 0; i < 4; i++) acc[mi][ni][i] = 0.f;
    float ssp = 0.f;

    float4 wv0, wv1, gv;
    float xv[2][4];

#define QKV_LOAD(k0) do { \
        gv  = *(const float4*)&gvec[(k0) + aq * 4]; \
        wv0 = *(const float4*)&w[(size_t)(row0 + am) * CDIM + (k0) + aq * 4]; \
        wv1 = *(const float4*)&w[(size_t)(row0 + am + 64) * CDIM + (k0) + aq * 4]; \
        _Pragma("unroll") \
        for (int j = 0; j < 2; j++) { \
            const float* xc = Bbase + (size_t)((k0) + (bc + 2 * j) * 4) * N_PIX + col0 + bp; \
            xv[j][0] = xc[0]; xv[j][1] = xc[N_PIX]; \
            xv[j][2] = xc[2 * N_PIX]; xv[j][3] = xc[3 * N_PIX]; \
        } \
    } while (0)

#define QKV_STORE(s) do { \
        uint2 oa0, oa1; \
        oa0.x = h2u(__floats2half2_rn(wv0.x * gv.x, wv0.y * gv.y)); \
        oa0.y = h2u(__floats2half2_rn(wv0.z * gv.z, wv0.w * gv.w)); \
        oa1.x = h2u(__floats2half2_rn(wv1.x * gv.x, wv1.y * gv.y)); \
        oa1.y = h2u(__floats2half2_rn(wv1.z * gv.z, wv1.w * gv.w)); \
        *(uint2*)&As[s][am * GP + aq * 2] = oa0; \
        *(uint2*)&As[s][(am + 64) * GP + aq * 2] = oa1; \
        _Pragma("unroll") \
        for (int j = 0; j < 2; j++) { \
            ssp += xv[j][0] * xv[j][0] + xv[j][1] * xv[j][1] \
                 + xv[j][2] * xv[j][2] + xv[j][3] * xv[j][3]; \
            uint2 ob; \
            ob.x = h2u(__floats2half2_rn(xv[j][0], xv[j][1])); \
            ob.y = h2u(__floats2half2_rn(xv[j][2], xv[j][3])); \
            *(uint2*)&Bs[s][bp * GP + (bc + 2 * j) * 2] = ob; \
        } \
    } while (0)

    QKV_LOAD(0);
    QKV_STORE(0);
    __syncthreads();

    for (int it = 0; it < 16; it++) {
        if (it < 15) QKV_LOAD((it + 1) * 16);
        int s = it & 1;
        uint32_t af[4][4];
#pragma unroll
        for (int mi = 0; mi < 4; mi++) {
            int r = (wm * 64 + mi * 16 + g) * GP;
            af[mi][0] = As[s][r + tig];
            af[mi][1] = As[s][r + 8 * GP + tig];
            af[mi][2] = As[s][r + tig + 4];
            af[mi][3] = As[s][r + 8 * GP + tig + 4];
        }
#pragma unroll
        for (int ni = 0; ni < 4; ni++) {
            int nb = (wn * 32 + ni * 8 + g) * GP;
            uint32_t b0 = Bs[s][nb + tig];
            uint32_t b1 = Bs[s][nb + tig + 4];
#pragma unroll
            for (int mi = 0; mi < 4; mi++)
                MMA_F16(acc[mi][ni], af[mi], b0, b1);
        }
        if (it < 15) QKV_STORE(s ^ 1);
        __syncthreads();
    }

    ssb[tid] = ssp;
    __syncthreads();

    int t = row0 >> 7;                  // 0=q 1=k 2=v
    float fac = (t == 0) ? (16.f * ATT_SCALE * LOG2E) : 16.f;
    float sc0[4], sc1[4];
#pragma unroll
    for (int ni = 0; ni < 4; ni++) {
        int pp = wn * 32 + ni * 8 + 2 * tig;
        float s0 = ssb[pp] + ssb[pp + 128];
        float s1 = ssb[pp + 1] + ssb[pp + 129];
        sc0[ni] = fac / fmaxf(sqrtf(s0), 1e-12f);
        sc1[ni] = fac / fmaxf(sqrtf(s1), 1e-12f);
    }
#pragma unroll
    for (int mi = 0; mi < 4; mi++) {
        int o_lo = row0 + wm * 64 + mi * 16 + g;
        int h = (o_lo >> 5) & 3;
        int f = o_lo & 31;
        size_t hb = (size_t)(b * NH + h);
#pragma unroll
        for (int ni = 0; ni < 4; ni++) {
            int p = col0 + wn * 32 + ni * 8 + 2 * tig;
            float c0 = acc[mi][ni][0] * sc0[ni], c1 = acc[mi][ni][1] * sc1[ni];
            float c2 = acc[mi][ni][2] * sc0[ni], c3 = acc[mi][ni][3] * sc1[ni];
            if (t < 2) {
                __half* d = ((t == 0) ? g_qh : g_kh) + hb * N_PIX * DH;
                d[(size_t)p * DH + f]           = __float2half_rn(c0);
                d[(size_t)(p + 1) * DH + f]     = __float2half_rn(c1);
                d[(size_t)p * DH + f + 8]       = __float2half_rn(c2);
                d[(size_t)(p + 1) * DH + f + 8] = __float2half_rn(c3);
            } else {
                __half* d = g_vh + hb * DH * N_PIX;
                *(__half2*)&d[(size_t)f * N_PIX + p]       = __floats2half2_rn(c0, c1);
                *(__half2*)&d[(size_t)(f + 8) * N_PIX + p] = __floats2half2_rn(c2, c3);
            }
        }
    }
}

// ---------------- kernel 2: flash attention, 8 warps x 16 q-rows ----------------
#define KPW 20
#define VPW 68
#define KWRD (128 * KPW)
#define VWRD (32 * VPW)
#define SMEM_FLASH ((2 * KWRD + 2 * VWRD) * 4)   // 37888 B

__global__ void __launch_bounds__(256) flash_mma() {
    extern __shared__ uint32_t sm[];
    int tid = threadIdx.x;
    int w   = tid >> 5, lane = tid & 31;
    int g   = lane >> 2, tig = lane & 3;

    int bh = blockIdx.y;
    int r0 = blockIdx.x * 128;
    int qb = r0 + w * 16;

    uint32_t sb = smem_u32(sm);
    const char* khp = (const char*)(g_kh + (size_t)bh * N_PIX * DH);
    const char* vhp = (const char*)(g_vh + (size_t)bh * DH * N_PIX);

    const __half* qp = g_qh + ((size_t)bh * N_PIX + qb) * DH;
    uint32_t qa[2][4];
#pragma unroll
    for (int kt = 0; kt < 2; kt++) {
        int ch = kt * 16 + 2 * tig;
        qa[kt][0] = *(const uint32_t*)&qp[g * DH + ch];
        qa[kt][1] = *(const uint32_t*)&qp[(g + 8) * DH + ch];
        qa[kt][2] = *(const uint32_t*)&qp[g * DH + ch + 8];
        qa[kt][3] = *(const uint32_t*)&qp[(g + 8) * DH + ch + 8];
    }

    float oacc[4][4];
#pragma unroll
    for (int nf = 0; nf < 4; nf++)
#pragma unroll
        for (int i = 0; i < 4; i++) oacc[nf][i] = 0.f;
    float lsum[2] = {0.f, 0.f};

    // stage tile 0
#pragma unroll
    for (int i = tid; i < 1024; i += 256) {
        if (i < 512) {
            int row = i >> 2, cc = i & 3;
            CP_ASYNC16(sb + row * (KPW * 4) + cc * 16, khp + row * 64 + cc * 16);
        } else {
            int j = i - 512, f = j >> 4, cc = j & 15;
            CP_ASYNC16(sb + 2 * KWRD * 4 + f * (VPW * 4) + cc * 16,
                       vhp + (size_t)f * 8192 + cc * 16);
        }
    }
    CP_COMMIT();

    for (int t = 0; t < 32; t++) {
        CP_WAIT0();
        __syncthreads();
        if (t < 31) {
            int nb = (t + 1) & 1;
            const char* ks = khp + (size_t)(t + 1) * 8192;
            const char* vs = vhp + (size_t)(t + 1) * 256;
            uint32_t kdst = sb + nb * KWRD * 4;
            uint32_t vdst = sb + (2 * KWRD + nb * VWRD) * 4;
#pragma unroll
            for (int i = tid; i < 1024; i += 256) {
                if (i < 512) {
                    int row = i >> 2, cc = i & 3;
                    CP_ASYNC16(kdst + row * (KPW * 4) + cc * 16, ks + row * 64 + cc * 16);
                } else {
                    int j = i - 512, f = j >> 4, cc = j & 15;
                    CP_ASYNC16(vdst + f * (VPW * 4) + cc * 16, vs + (size_t)f * 8192 + cc * 16);
                }
            }
            CP_COMMIT();
        }
        const uint32_t* Ks = sm + (t & 1) * KWRD;
        const uint32_t* Vt = sm + 2 * KWRD + (t & 1) * VWRD;

#pragma unroll
        for (int chk = 0; chk < 4; chk++) {
            // S chunk: 16 q-rows x 32 kv
            float sacc[4][4];
#pragma unroll
            for (int ni = 0; ni < 4; ni++)
#pragma unroll
                for (int i = 0; i < 4; i++) sacc[ni][i] = 0.f;
#pragma unroll
            for (int kt = 0; kt < 2; kt++)
#pragma unroll
                for (int ni = 0; ni < 4; ni++) {
                    int kv = chk * 32 + ni * 8 + g;
                    uint32_t b0 = Ks[kv * KPW + kt * 8 + tig];
                    uint32_t b1 = Ks[kv * KPW + kt * 8 + tig + 4];
                    MMA_F16(sacc[ni], qa[kt], b0, b1);
                }
            // P = 2^S packed directly into O-MMA A-fragments
            uint32_t pf[4][2];
#pragma unroll
            for (int ni = 0; ni < 4; ni++) {
                float p0 = ex2f(sacc[ni][0]);
                float p1 = ex2f(sacc[ni][1]);
                float p2 = ex2f(sacc[ni][2]);
                float p3 = ex2f(sacc[ni][3]);
                lsum[0] += p0 + p1;
                lsum[1] += p2 + p3;
                pf[ni][0] = h2u(__floats2half2_rn(p0, p1));   // row g
                pf[ni][1] = h2u(__floats2half2_rn(p2, p3));   // row g+8
            }
            // O += P_chunk(16x32) * V_chunk(32f x 32kv)^T
#pragma unroll
            for (int kt = 0; kt < 2; kt++) {
                uint32_t pa[4];
                pa[0] = pf[2 * kt][0];
                pa[1] = pf[2 * kt][1];
                pa[2] = pf[2 * kt + 1][0];
                pa[3] = pf[2 * kt + 1][1];
#pragma unroll
                for (int nf = 0; nf < 4; nf++) {
                    int fb = (nf * 8 + g) * VPW + chk * 16 + kt * 8 + tig;
                    uint32_t b0 = Vt[fb];
                    uint32_t b1 = Vt[fb + 4];
                    MMA_F16(oacc[nf], pa, b0, b1);
                }
            }
        }
    }

    float inv[2];
#pragma unroll
    for (int hf = 0; hf < 2; hf++) {
        float v = lsum[hf];
        v += __shfl_xor_sync(0xFFFFFFFF, v, 1);
        v += __shfl_xor_sync(0xFFFFFFFF, v, 2);
        inv[hf] = ATT_SCALE / v;     // second SCALE folded here
    }

    int b = bh >> 2, h = bh & 3;
    __half* ao = g_aoh + (size_t)b * N_PIX * HID + h * DH;
#pragma unroll
    for (int nf = 0; nf < 4; nf++) {
        int f = nf * 8 + 2 * tig;
        int rlo = qb + g, rhi = rlo + 8;
        *(__half2*)&ao[(size_t)rlo * HID + f] =
            __floats2half2_rn(oacc[nf][0] * inv[0], oacc[nf][1] * inv[0]);
        *(__half2*)&ao[(size_t)rhi * HID + f] =
            __floats2half2_rn(oacc[nf][2] * inv[1], oacc[nf][3] * inv[1]);
    }
}

// ---------------- kernel 3: output projection, 64x128 tiles, pipelined ----------------
__global__ void __launch_bounds__(256) out_mma(const float* __restrict__ w,
                                               const float* __restrict__ bias,
                                               float* __restrict__ out) {
    __shared__ uint32_t As[2][64 * GP];
    __shared__ uint32_t Bs[2][128 * GP];
    int b = blockIdx.z, row0 = blockIdx.y * 64, col0 = blockIdx.x * 128;
    int tid = threadIdx.x, wid = tid >> 5, lane = tid & 31;
    int wm = wid >> 2, wn = wid & 3;
    int g = lane >> 2, tig = lane & 3;
    const __half* Bbase = g_aoh + (size_t)b * N_PIX * HID;

    int am = tid >> 2, aq = tid & 3;     // A: row am (0..63), col quad aq
    int bp = tid & 127, bq = tid >> 7;   // B: pixel bp; k-quads bq, bq+2

    float acc[2][4][4];
#pragma unroll
    for (int mi = 0; mi < 2; mi++)
#pragma unroll
        for (int ni = 0; ni < 4; ni++)
#pragma unroll
            for (int i = 0; i < 4; i++) acc[mi][ni][i] = 0.f;

    float4 wv;
    uint2 bv[2];

#define OUT_LOAD(k0) do { \
        wv = *(const float4*)&w[(size_t)(row0 + am) * HID + (k0) + aq * 4]; \
        bv[0] = *(const uint2*)&Bbase[(size_t)(col0 + bp) * HID + (k0) + bq * 4]; \
        bv[1] = *(const uint2*)&Bbase[(size_t)(col0 + bp) * HID + (k0) + (bq + 2) * 4]; \
    } while (0)

#define OUT_STORE(s) do { \
        uint2 oa; \
        oa.x = h2u(__floats2half2_rn(wv.x, wv.y)); \
        oa.y = h2u(__floats2half2_rn(wv.z, wv.w)); \
        *(uint2*)&As[s][am * GP + aq * 2] = oa; \
        *(uint2*)&Bs[s][bp * GP + bq * 2] = bv[0]; \
        *(uint2*)&Bs[s][bp * GP + (bq + 2) * 2] = bv[1]; \
    } while (0)

    OUT_LOAD(0);
    OUT_STORE(0);
    __syncthreads();

    for (int it = 0; it < 8; it++) {
        if (it < 7) OUT_LOAD((it + 1) * 16);
        int s = it & 1;
        uint32_t af[2][4];
#pragma unroll
        for (int mi = 0; mi < 2; mi++) {
            int r = (wm * 32 + mi * 16 + g) * GP;
            af[mi][0] = As[s][r + tig];
            af[mi][1] = As[s][r + 8 * GP + tig];
            af[mi][2] = As[s][r + tig + 4];
            af[mi][3] = As[s][r + 8 * GP + tig + 4];
        }
#pragma unroll
        for (int ni = 0; ni < 4; ni++) {
            int nb = (wn * 32 + ni * 8 + g) * GP;
            uint32_t b0 = Bs[s][nb + tig];
            uint32_t b1 = Bs[s][nb + tig + 4];
#pragma unroll
            for (int mi = 0; mi < 2; mi++)
                MMA_F16(acc[mi][ni], af[mi], b0, b1);
        }
        if (it < 7) OUT_STORE(s ^ 1);
        __syncthreads();
    }

#pragma unroll
    for (int mi = 0; mi < 2; mi++) {
        int o_lo = row0 + wm * 32 + mi * 16 + g;
        float b0v = bias[o_lo], b1v = bias[o_lo + 8];
        float* r0p = out + ((size_t)b * CDIM + o_lo) * N_PIX;
        float* r1p = r0p + 8 * N_PIX;
#pragma unroll
        for (int ni = 0; ni < 4; ni++) {
            int p = col0 + wn * 32 + ni * 8 + 2 * tig;
            *(float2*)&r0p[p] = make_float2(acc[mi][ni][0] + b0v, acc[mi][ni][1] + b0v);
            *(float2*)&r1p[p] = make_float2(acc[mi][ni][2] + b1v, acc[mi][ni][3] + b1v);
        }
    }
}

// ---------------- launcher ----------------
extern "C" void kernel_launch(void* const* d_in, const int* in_sizes, int n_in,
                              void* d_out, int out_size) {
    const float* x     = (const float*)d_in[0];
    const float* gvec  = (const float*)d_in[1];
    const float* w_qkv = (const float*)d_in[2];
    const float* w_out = (const float*)d_in[3];
    const float* b_out = (const float*)d_in[4];
    float* out = (float*)d_out;

    static int smem_set = 0;
    if (!smem_set) {
        cudaFuncSetAttribute(flash_mma, cudaFuncAttributeMaxDynamicSharedMemorySize,
                             SMEM_FLASH);
        smem_set = 1;
    }

    dim3 g1(N_PIX / 128, 3, BATCH);               // 32 x 3 x 2
    qkv_mma<<<g1, 256>>>(x, gvec, w_qkv);

    dim3 g2(N_PIX / 128, BATCH * NH);             // 32 x 8
    flash_mma<<<g2, 256, SMEM_FLASH>>>();

    dim3 g3(N_PIX / 128, CDIM / 64, BATCH);       // 32 x 4 x 2
    out_mma<<<g3, 256>>>(w_out, b_out, out);
}

// round 10
// speedup vs baseline: 1.0216x; 1.0216x over previous
#include <cuda_runtime.h>
#include <cuda_fp16.h>
#include <math.h>
#include <stdint.h>

#define N_PIX 4096
#define CDIM  256
#define HID   128
#define NH    4
#define DH    32
#define BATCH 2
#define ATT_SCALE 0.17677669529663687f   // 32^-0.5
#define LOG2E     1.4426950408889634f
#define ONES_H2   0x3C003C00u            // f16x2 (1.0, 1.0)

// ---------------- scratch (static device globals; no allocs) ----------------
__device__ __half g_qh [BATCH * NH * N_PIX * DH];   // [bh][n][f], pre-scaled by ATT_SCALE*LOG2E
__device__ __half g_kh [BATCH * NH * N_PIX * DH];   // [bh][n][f]
__device__ __half g_vh [BATCH * NH * DH * N_PIX];   // [bh][f][n]  (transposed)
__device__ __half g_aoh[BATCH * N_PIX * HID];       // [b][n][h*32+f]  (n-major)

__device__ __forceinline__ uint32_t smem_u32(const void* p) {
    uint32_t a;
    asm("{ .reg .u64 t; cvta.to.shared.u64 t, %1; cvt.u32.u64 %0, t; }" : "=r"(a) : "l"(p));
    return a;
}
__device__ __forceinline__ uint32_t h2u(__half2 h) { return *(uint32_t*)&h; }
__device__ __forceinline__ uint32_t ex2_h2(uint32_t x) {
    uint32_t r;
    asm("ex2.approx.f16x2 %0, %1;" : "=r"(r) : "r"(x));
    return r;
}

#define MMA_F16(c, a, b0_, b1_) \
    asm volatile("mma.sync.aligned.m16n8k16.row.col.f32.f16.f16.f32 " \
        "{%0,%1,%2,%3},{%4,%5,%6,%7},{%8,%9},{%0,%1,%2,%3};" \
        : "+f"((c)[0]), "+f"((c)[1]), "+f"((c)[2]), "+f"((c)[3]) \
        : "r"((a)[0]), "r"((a)[1]), "r"((a)[2]), "r"((a)[3]), "r"(b0_), "r"(b1_))
#define CP_ASYNC16(dst, src) \
    asm volatile("cp.async.ca.shared.global [%0], [%1], 16;" :: "r"(dst), "l"(src))
#define CP_COMMIT() asm volatile("cp.async.commit_group;" ::: "memory")
#define CP_WAIT0()  asm volatile("cp.async.wait_group 0;"  ::: "memory")

// ---------------- kernel 1: QKV GEMM, norm fused, software-pipelined ----------------
#define GP 12     // smem pitch in uint32 (8 half2 data + 4 pad)
__global__ void __launch_bounds__(256) qkv_mma(const float* __restrict__ x,
                                               const float* __restrict__ gvec,
                                               const float* __restrict__ w) {
    __shared__ uint32_t As[2][128 * GP];
    __shared__ uint32_t Bs[2][128 * GP];
    __shared__ float ssb[256];
    int b = blockIdx.z, row0 = blockIdx.y * 128, col0 = blockIdx.x * 128;
    int tid = threadIdx.x, wid = tid >> 5, lane = tid & 31;
    int wm = wid >> 2, wn = wid & 3;
    int g = lane >> 2, tig = lane & 3;
    const float* Bbase = x + (size_t)b * CDIM * N_PIX;

    int am = tid >> 2, aq = tid & 3;
    int bp = tid & 127, bc = tid >> 7;

    float acc[4][4][4];
#pragma unroll
    for (int mi = 0; mi < 4; mi++)
#pragma unroll
        for (int ni = 0; ni < 4; ni++)
#pragma unroll
            for (int i = 0; i < 4; i++) acc[mi][ni][i] = 0.f;
    float ssp = 0.f;

    float4 wv0, wv1, gv;
    float xv[2][4];

#define QKV_LOAD(k0) do { \
        gv  = *(const float4*)&gvec[(k0) + aq * 4]; \
        wv0 = *(const float4*)&w[(size_t)(row0 + am) * CDIM + (k0) + aq * 4]; \
        wv1 = *(const float4*)&w[(size_t)(row0 + am + 64) * CDIM + (k0) + aq * 4]; \
        _Pragma("unroll") \
        for (int j = 0; j < 2; j++) { \
            const float* xc = Bbase + (size_t)((k0) + (bc + 2 * j) * 4) * N_PIX + col0 + bp; \
            xv[j][0] = xc[0]; xv[j][1] = xc[N_PIX]; \
            xv[j][2] = xc[2 * N_PIX]; xv[j][3] = xc[3 * N_PIX]; \
        } \
    } while (0)

#define QKV_STORE(s) do { \
        uint2 oa0, oa1; \
        oa0.x = h2u(__floats2half2_rn(wv0.x * gv.x, wv0.y * gv.y)); \
        oa0.y = h2u(__floats2half2_rn(wv0.z * gv.z, wv0.w * gv.w)); \
        oa1.x = h2u(__floats2half2_rn(wv1.x * gv.x, wv1.y * gv.y)); \
        oa1.y = h2u(__floats2half2_rn(wv1.z * gv.z, wv1.w * gv.w)); \
        *(uint2*)&As[s][am * GP + aq * 2] = oa0; \
        *(uint2*)&As[s][(am + 64) * GP + aq * 2] = oa1; \
        _Pragma("unroll") \
        for (int j = 0; j < 2; j++) { \
            ssp += xv[j][0] * xv[j][0] + xv[j][1] * xv[j][1] \
                 + xv[j][2] * xv[j][2] + xv[j][3] * xv[j][3]; \
            uint2 ob; \
            ob.x = h2u(__floats2half2_rn(xv[j][0], xv[j][1])); \
            ob.y = h2u(__floats2half2_rn(xv[j][2], xv[j][3])); \
            *(uint2*)&Bs[s][bp * GP + (bc + 2 * j) * 2] = ob; \
        } \
    } while (0)

    QKV_LOAD(0);
    QKV_STORE(0);
    __syncthreads();

    for (int it = 0; it < 16; it++) {
        if (it < 15) QKV_LOAD((it + 1) * 16);
        int s = it & 1;
        uint32_t af[4][4];
#pragma unroll
        for (int mi = 0; mi < 4; mi++) {
            int r = (wm * 64 + mi * 16 + g) * GP;
            af[mi][0] = As[s][r + tig];
            af[mi][1] = As[s][r + 8 * GP + tig];
            af[mi][2] = As[s][r + tig + 4];
            af[mi][3] = As[s][r + 8 * GP + tig + 4];
        }
#pragma unroll
        for (int ni = 0; ni < 4; ni++) {
            int nb = (wn * 32 + ni * 8 + g) * GP;
            uint32_t b0 = Bs[s][nb + tig];
            uint32_t b1 = Bs[s][nb + tig + 4];
#pragma unroll
            for (int mi = 0; mi < 4; mi++)
                MMA_F16(acc[mi][ni], af[mi], b0, b1);
        }
        if (it < 15) QKV_STORE(s ^ 1);
        __syncthreads();
    }

    ssb[tid] = ssp;
    __syncthreads();

    int t = row0 >> 7;                  // 0=q 1=k 2=v
    float fac = (t == 0) ? (16.f * ATT_SCALE * LOG2E) : 16.f;
    float sc0[4], sc1[4];
#pragma unroll
    for (int ni = 0; ni < 4; ni++) {
        int pp = wn * 32 + ni * 8 + 2 * tig;
        float s0 = ssb[pp] + ssb[pp + 128];
        float s1 = ssb[pp + 1] + ssb[pp + 129];
        sc0[ni] = fac / fmaxf(sqrtf(s0), 1e-12f);
        sc1[ni] = fac / fmaxf(sqrtf(s1), 1e-12f);
    }
#pragma unroll
    for (int mi = 0; mi < 4; mi++) {
        int o_lo = row0 + wm * 64 + mi * 16 + g;
        int h = (o_lo >> 5) & 3;
        int f = o_lo & 31;
        size_t hb = (size_t)(b * NH + h);
#pragma unroll
        for (int ni = 0; ni < 4; ni++) {
            int p = col0 + wn * 32 + ni * 8 + 2 * tig;
            float c0 = acc[mi][ni][0] * sc0[ni], c1 = acc[mi][ni][1] * sc1[ni];
            float c2 = acc[mi][ni][2] * sc0[ni], c3 = acc[mi][ni][3] * sc1[ni];
            if (t < 2) {
                __half* d = ((t == 0) ? g_qh : g_kh) + hb * N_PIX * DH;
                d[(size_t)p * DH + f]           = __float2half_rn(c0);
                d[(size_t)(p + 1) * DH + f]     = __float2half_rn(c1);
                d[(size_t)p * DH + f + 8]       = __float2half_rn(c2);
                d[(size_t)(p + 1) * DH + f + 8] = __float2half_rn(c3);
            } else {
                __half* d = g_vh + hb * DH * N_PIX;
                *(__half2*)&d[(size_t)f * N_PIX + p]       = __floats2half2_rn(c0, c1);
                *(__half2*)&d[(size_t)(f + 8) * N_PIX + p] = __floats2half2_rn(c2, c3);
            }
        }
    }
}

// ---------------- kernel 2: flash attention, f16x2 exp + MMA row-sums ----------------
#define KPW 20
#define VPW 68
#define KWRD (128 * KPW)
#define VWRD (32 * VPW)
#define SMEM_FLASH ((2 * KWRD + 2 * VWRD) * 4)   // 37888 B

__global__ void __launch_bounds__(256) flash_mma() {
    extern __shared__ uint32_t sm[];
    int tid = threadIdx.x;
    int w   = tid >> 5, lane = tid & 31;
    int g   = lane >> 2, tig = lane & 3;

    int bh = blockIdx.y;
    int r0 = blockIdx.x * 128;
    int qb = r0 + w * 16;

    uint32_t sb = smem_u32(sm);
    const char* khp = (const char*)(g_kh + (size_t)bh * N_PIX * DH);
    const char* vhp = (const char*)(g_vh + (size_t)bh * DH * N_PIX);

    const __half* qp = g_qh + ((size_t)bh * N_PIX + qb) * DH;
    uint32_t qa[2][4];
#pragma unroll
    for (int kt = 0; kt < 2; kt++) {
        int ch = kt * 16 + 2 * tig;
        qa[kt][0] = *(const uint32_t*)&qp[g * DH + ch];
        qa[kt][1] = *(const uint32_t*)&qp[(g + 8) * DH + ch];
        qa[kt][2] = *(const uint32_t*)&qp[g * DH + ch + 8];
        qa[kt][3] = *(const uint32_t*)&qp[(g + 8) * DH + ch + 8];
    }

    float oacc[4][4];
#pragma unroll
    for (int nf = 0; nf < 4; nf++)
#pragma unroll
        for (int i = 0; i < 4; i++) oacc[nf][i] = 0.f;
    float lacc[4] = {0.f, 0.f, 0.f, 0.f};   // ones-MMA row sums: [0]=row g, [2]=row g+8

    // stage tile 0
#pragma unroll
    for (int i = tid; i < 1024; i += 256) {
        if (i < 512) {
            int row = i >> 2, cc = i & 3;
            CP_ASYNC16(sb + row * (KPW * 4) + cc * 16, khp + row * 64 + cc * 16);
        } else {
            int j = i - 512, f = j >> 4, cc = j & 15;
            CP_ASYNC16(sb + 2 * KWRD * 4 + f * (VPW * 4) + cc * 16,
                       vhp + (size_t)f * 8192 + cc * 16);
        }
    }
    CP_COMMIT();

    for (int t = 0; t < 32; t++) {
        CP_WAIT0();
        __syncthreads();
        if (t < 31) {
            int nb = (t + 1) & 1;
            const char* ks = khp + (size_t)(t + 1) * 8192;
            const char* vs = vhp + (size_t)(t + 1) * 256;
            uint32_t kdst = sb + nb * KWRD * 4;
            uint32_t vdst = sb + (2 * KWRD + nb * VWRD) * 4;
#pragma unroll
            for (int i = tid; i < 1024; i += 256) {
                if (i < 512) {
                    int row = i >> 2, cc = i & 3;
                    CP_ASYNC16(kdst + row * (KPW * 4) + cc * 16, ks + row * 64 + cc * 16);
                } else {
                    int j = i - 512, f = j >> 4, cc = j & 15;
                    CP_ASYNC16(vdst + f * (VPW * 4) + cc * 16, vs + (size_t)f * 8192 + cc * 16);
                }
            }
            CP_COMMIT();
        }
        const uint32_t* Ks = sm + (t & 1) * KWRD;
        const uint32_t* Vt = sm + 2 * KWRD + (t & 1) * VWRD;

#pragma unroll
        for (int chk = 0; chk < 4; chk++) {
            // S chunk: 16 q-rows x 32 kv
            float sacc[4][4];
#pragma unroll
            for (int ni = 0; ni < 4; ni++)
#pragma unroll
                for (int i = 0; i < 4; i++) sacc[ni][i] = 0.f;
#pragma unroll
            for (int kt = 0; kt < 2; kt++)
#pragma unroll
                for (int ni = 0; ni < 4; ni++) {
                    int kv = chk * 32 + ni * 8 + g;
                    uint32_t b0 = Ks[kv * KPW + kt * 8 + tig];
                    uint32_t b1 = Ks[kv * KPW + kt * 8 + tig + 4];
                    MMA_F16(sacc[ni], qa[kt], b0, b1);
                }
            // P = 2^S: pack to f16x2 then one MUFU per pair (half the MUFU ops)
            uint32_t pf[4][2];
#pragma unroll
            for (int ni = 0; ni < 4; ni++) {
                pf[ni][0] = ex2_h2(h2u(__floats2half2_rn(sacc[ni][0], sacc[ni][1])));
                pf[ni][1] = ex2_h2(h2u(__floats2half2_rn(sacc[ni][2], sacc[ni][3])));
            }
            // O += P * V^T; lacc += P * ones (exact f16-P row sums, fp32 accum)
#pragma unroll
            for (int kt = 0; kt < 2; kt++) {
                uint32_t pa[4];
                pa[0] = pf[2 * kt][0];
                pa[1] = pf[2 * kt][1];
                pa[2] = pf[2 * kt + 1][0];
                pa[3] = pf[2 * kt + 1][1];
#pragma unroll
                for (int nf = 0; nf < 4; nf++) {
                    int fb = (nf * 8 + g) * VPW + chk * 16 + kt * 8 + tig;
                    uint32_t b0 = Vt[fb];
                    uint32_t b1 = Vt[fb + 4];
                    MMA_F16(oacc[nf], pa, b0, b1);
                }
                MMA_F16(lacc, pa, ONES_H2, ONES_H2);
            }
        }
    }

    // lacc[0] = full row-sum for row g, lacc[2] for row g+8 (no shuffle needed)
    float inv0 = ATT_SCALE / lacc[0];
    float inv1 = ATT_SCALE / lacc[2];

    int b = bh >> 2, h = bh & 3;
    __half* ao = g_aoh + (size_t)b * N_PIX * HID + h * DH;
#pragma unroll
    for (int nf = 0; nf < 4; nf++) {
        int f = nf * 8 + 2 * tig;
        int rlo = qb + g, rhi = rlo + 8;
        *(__half2*)&ao[(size_t)rlo * HID + f] =
            __floats2half2_rn(oacc[nf][0] * inv0, oacc[nf][1] * inv0);
        *(__half2*)&ao[(size_t)rhi * HID + f] =
            __floats2half2_rn(oacc[nf][2] * inv1, oacc[nf][3] * inv1);
    }
}

// ---------------- kernel 3: output projection, 64x128 tiles, pipelined ----------------
__global__ void __launch_bounds__(256) out_mma(const float* __restrict__ w,
                                               const float* __restrict__ bias,
                                               float* __restrict__ out) {
    __shared__ uint32_t As[2][64 * GP];
    __shared__ uint32_t Bs[2][128 * GP];
    int b = blockIdx.z, row0 = blockIdx.y * 64, col0 = blockIdx.x * 128;
    int tid = threadIdx.x, wid = tid >> 5, lane = tid & 31;
    int wm = wid >> 2, wn = wid & 3;
    int g = lane >> 2, tig = lane & 3;
    const __half* Bbase = g_aoh + (size_t)b * N_PIX * HID;

    int am = tid >> 2, aq = tid & 3;
    int bp = tid & 127, bq = tid >> 7;

    float acc[2][4][4];
#pragma unroll
    for (int mi = 0; mi < 2; mi++)
#pragma unroll
        for (int ni = 0; ni < 4; ni++)
#pragma unroll
            for (int i = 0; i < 4; i++) acc[mi][ni][i] = 0.f;

    float4 wv;
    uint2 bv[2];

#define OUT_LOAD(k0) do { \
        wv = *(const float4*)&w[(size_t)(row0 + am) * HID + (k0) + aq * 4]; \
        bv[0] = *(const uint2*)&Bbase[(size_t)(col0 + bp) * HID + (k0) + bq * 4]; \
        bv[1] = *(const uint2*)&Bbase[(size_t)(col0 + bp) * HID + (k0) + (bq + 2) * 4]; \
    } while (0)

#define OUT_STORE(s) do { \
        uint2 oa; \
        oa.x = h2u(__floats2half2_rn(wv.x, wv.y)); \
        oa.y = h2u(__floats2half2_rn(wv.z, wv.w)); \
        *(uint2*)&As[s][am * GP + aq * 2] = oa; \
        *(uint2*)&Bs[s][bp * GP + bq * 2] = bv[0]; \
        *(uint2*)&Bs[s][bp * GP + (bq + 2) * 2] = bv[1]; \
    } while (0)

    OUT_LOAD(0);
    OUT_STORE(0);
    __syncthreads();

    for (int it = 0; it < 8; it++) {
        if (it < 7) OUT_LOAD((it + 1) * 16);
        int s = it & 1;
        uint32_t af[2][4];
#pragma unroll
        for (int mi = 0; mi < 2; mi++) {
            int r = (wm * 32 + mi * 16 + g) * GP;
            af[mi][0] = As[s][r + tig];
            af[mi][1] = As[s][r + 8 * GP + tig];
            af[mi][2] = As[s][r + tig + 4];
            af[mi][3] = As[s][r + 8 * GP + tig + 4];
        }
#pragma unroll
        for (int ni = 0; ni < 4; ni++) {
            int nb = (wn * 32 + ni * 8 + g) * GP;
            uint32_t b0 = Bs[s][nb + tig];
            uint32_t b1 = Bs[s][nb + tig + 4];
#pragma unroll
            for (int mi = 0; mi < 2; mi++)
                MMA_F16(acc[mi][ni], af[mi], b0, b1);
        }
        if (it < 7) OUT_STORE(s ^ 1);
        __syncthreads();
    }

#pragma unroll
    for (int mi = 0; mi < 2; mi++) {
        int o_lo = row0 + wm * 32 + mi * 16 + g;
        float b0v = bias[o_lo], b1v = bias[o_lo + 8];
        float* r0p = out + ((size_t)b * CDIM + o_lo) * N_PIX;
        float* r1p = r0p + 8 * N_PIX;
#pragma unroll
        for (int ni = 0; ni < 4; ni++) {
            int p = col0 + wn * 32 + ni * 8 + 2 * tig;
            *(float2*)&r0p[p] = make_float2(acc[mi][ni][0] + b0v, acc[mi][ni][1] + b0v);
            *(float2*)&r1p[p] = make_float2(acc[mi][ni][2] + b1v, acc[mi][ni][3] + b1v);
        }
    }
}

// ---------------- launcher ----------------
extern "C" void kernel_launch(void* const* d_in, const int* in_sizes, int n_in,
                              void* d_out, int out_size) {
    const float* x     = (const float*)d_in[0];
    const float* gvec  = (const float*)d_in[1];
    const float* w_qkv = (const float*)d_in[2];
    const float* w_out = (const float*)d_in[3];
    const float* b_out = (const float*)d_in[4];
    float* out = (float*)d_out;

    static int smem_set = 0;
    if (!smem_set) {
        cudaFuncSetAttribute(flash_mma, cudaFuncAttributeMaxDynamicSharedMemorySize,
                             SMEM_FLASH);
        smem_set = 1;
    }

    dim3 g1(N_PIX / 128, 3, BATCH);               // 32 x 3 x 2
    qkv_mma<<<g1, 256>>>(x, gvec, w_qkv);

    dim3 g2(N_PIX / 128, BATCH * NH);             // 32 x 8
    flash_mma<<<g2, 256, SMEM_FLASH>>>();

    dim3 g3(N_PIX / 128, CDIM / 64, BATCH);       // 32 x 4 x 2
    out_mma<<<g3, 256>>>(w_out, b_out, out);
}